// round 1
// baseline (speedup 1.0000x reference)
#include <cuda_runtime.h>
#include <cuda_bf16.h>
#include <math.h>

// Problem constants
#define T_ 1024
#define B_ 8
#define E_ 512
#define H_ 8
#define D_ 64
#define BH_ 64          // B*H
#define TB_ 8192        // T*B
#define NQKV_ 1536      // 3*E
#define SCALE_ 0.125f   // D^-0.5
#define INV_H_ 0.125f

#define TBE_ (T_ * B_ * E_)          // 4,194,304
#define BTT_ (B_ * T_ * T_)          // 8,388,608
#define OUT_AW_OFF_ (2 * TBE_)       // start of aw stack in d_out

// ---------------------------------------------------------------------------
// Scratch (device globals; no runtime allocation allowed)
// ---------------------------------------------------------------------------
__device__ float g_qkv_r[TB_ * NQKV_];
__device__ float g_qkv_i[TB_ * NQKV_];
__device__ float g_attn_r[TB_ * E_];
__device__ float g_attn_i[TB_ * E_];

// ---------------------------------------------------------------------------
// Zero-fill kernel (aw-average region must start at 0 for atomic accumulation)
// ---------------------------------------------------------------------------
__global__ void zero_kernel(float* __restrict__ p, int n) {
    int i = blockIdx.x * blockDim.x + threadIdx.x;
    if (i < n) p[i] = 0.0f;
}

// ---------------------------------------------------------------------------
// Complex GEMM:  Y = X @ W^T + b   (complex), X:[M,K], W:[N,K], Y:[M,N]
//   Yr = Xr Wr^T - Xi Wi^T + br
//   Yi = Xi Wr^T + Xr Wi^T + bi
// Tiling: 64x64 block, BK=16, 256 threads, 4x4 per thread.
// ---------------------------------------------------------------------------
__global__ __launch_bounds__(256) void cgemm64(
    const float* __restrict__ Xr, const float* __restrict__ Xi,
    const float* __restrict__ Wr, const float* __restrict__ Wi,
    const float* __restrict__ br, const float* __restrict__ bi,
    float* __restrict__ Yr, float* __restrict__ Yi,
    int M, int N, int K)
{
    __shared__ float sXr[16][68], sXi[16][68], sWr[16][68], sWi[16][68];

    const int tid  = threadIdx.x;
    const int row0 = blockIdx.y * 64;
    const int col0 = blockIdx.x * 64;
    const int lr = tid >> 2;            // 0..63
    const int lk = (tid & 3) << 2;      // 0,4,8,12
    const int ty = tid >> 4;            // 0..15
    const int tx = tid & 15;            // 0..15

    float accr[4][4], acci[4][4];
#pragma unroll
    for (int i = 0; i < 4; i++)
#pragma unroll
        for (int j = 0; j < 4; j++) { accr[i][j] = 0.f; acci[i][j] = 0.f; }

    for (int k0 = 0; k0 < K; k0 += 16) {
        float4 v;
        v = *reinterpret_cast<const float4*>(&Xr[(row0 + lr) * K + k0 + lk]);
        sXr[lk + 0][lr] = v.x; sXr[lk + 1][lr] = v.y; sXr[lk + 2][lr] = v.z; sXr[lk + 3][lr] = v.w;
        v = *reinterpret_cast<const float4*>(&Xi[(row0 + lr) * K + k0 + lk]);
        sXi[lk + 0][lr] = v.x; sXi[lk + 1][lr] = v.y; sXi[lk + 2][lr] = v.z; sXi[lk + 3][lr] = v.w;
        v = *reinterpret_cast<const float4*>(&Wr[(col0 + lr) * K + k0 + lk]);
        sWr[lk + 0][lr] = v.x; sWr[lk + 1][lr] = v.y; sWr[lk + 2][lr] = v.z; sWr[lk + 3][lr] = v.w;
        v = *reinterpret_cast<const float4*>(&Wi[(col0 + lr) * K + k0 + lk]);
        sWi[lk + 0][lr] = v.x; sWi[lk + 1][lr] = v.y; sWi[lk + 2][lr] = v.z; sWi[lk + 3][lr] = v.w;
        __syncthreads();

#pragma unroll
        for (int k = 0; k < 16; k++) {
            float ar[4], ai[4], wr[4], wi[4];
            *reinterpret_cast<float4*>(ar) = *reinterpret_cast<const float4*>(&sXr[k][ty << 2]);
            *reinterpret_cast<float4*>(ai) = *reinterpret_cast<const float4*>(&sXi[k][ty << 2]);
            *reinterpret_cast<float4*>(wr) = *reinterpret_cast<const float4*>(&sWr[k][tx << 2]);
            *reinterpret_cast<float4*>(wi) = *reinterpret_cast<const float4*>(&sWi[k][tx << 2]);
#pragma unroll
            for (int i = 0; i < 4; i++)
#pragma unroll
                for (int j = 0; j < 4; j++) {
                    accr[i][j] += ar[i] * wr[j] - ai[i] * wi[j];
                    acci[i][j] += ai[i] * wr[j] + ar[i] * wi[j];
                }
        }
        __syncthreads();
    }

    const float4 b4r = *reinterpret_cast<const float4*>(&br[col0 + (tx << 2)]);
    const float4 b4i = *reinterpret_cast<const float4*>(&bi[col0 + (tx << 2)]);
#pragma unroll
    for (int i = 0; i < 4; i++) {
        const int row = row0 + (ty << 2) + i;
        float4 orr, oii;
        orr.x = accr[i][0] + b4r.x; orr.y = accr[i][1] + b4r.y;
        orr.z = accr[i][2] + b4r.z; orr.w = accr[i][3] + b4r.w;
        oii.x = acci[i][0] + b4i.x; oii.y = acci[i][1] + b4i.y;
        oii.z = acci[i][2] + b4i.z; oii.w = acci[i][3] + b4i.w;
        *reinterpret_cast<float4*>(&Yr[row * N + col0 + (tx << 2)]) = orr;
        *reinterpret_cast<float4*>(&Yi[row * N + col0 + (tx << 2)]) = oii;
    }
}

// ---------------------------------------------------------------------------
// Fused attention: per CTA = (16 q-rows, one (b,h) head).
//   phase 1: scores s1=(qr.kr+qi.ki)*SCALE, s2=(qi.kr-qr.ki)*SCALE -> SMEM
//   phase 2: row softmax (both), atomic accumulate head-average into d_out
//   phase 3: attn_r = aw_r V_r + aw_i V_i ; attn_i = aw_i V_r - aw_r V_i
// SMEM: s1,s2 [16][1024]; q transposed [64][16]; k/v chunk double-use buffer.
// ---------------------------------------------------------------------------
#define ATTN_SMEM_FLOATS (2*16*1024 + 2*1024 + 2*8704)
#define ATTN_SMEM_BYTES  (ATTN_SMEM_FLOATS * 4)

__global__ __launch_bounds__(256) void attn_kernel(
    const float* __restrict__ qkvr, const float* __restrict__ qkvi,
    float* __restrict__ attnr, float* __restrict__ attni,
    float* __restrict__ aw_out)
{
    extern __shared__ float sh[];
    float* s1   = sh;                       // [16][1024]
    float* s2   = s1 + 16 * 1024;           // [16][1024]
    float* qtr  = s2 + 16 * 1024;           // [64][16]  (q real, transposed)
    float* qti  = qtr + 1024;               // [64][16]
    float* bufA = qti + 1024;               // k_r^T [64][132] OR v_r [128][68]
    float* bufB = bufA + 8704;              // k_i^T OR v_i

    const int tid  = threadIdx.x;
    const int tBlk = blockIdx.x * 16;       // first q row of this tile
    const int bh   = blockIdx.y;
    const int b    = bh >> 3;
    const int h    = bh & 7;

    // ---- load q tile (transposed) ----
    for (int idx = tid; idx < 1024; idx += 256) {
        const int t = idx >> 6, d = idx & 63;
        const int g = ((tBlk + t) * B_ + b) * NQKV_ + h * D_ + d;
        qtr[d * 16 + t] = qkvr[g];
        qti[d * 16 + t] = qkvi[g];
    }

    // ---- phase 1: scores ----
    {
        const int t0 = (tid >> 5) * 2;       // 2 q-rows per thread
        const int sj = (tid & 31) * 4;       // 4 s-cols per thread (chunk of 128)
        for (int s0 = 0; s0 < 1024; s0 += 128) {
            __syncthreads();
            // stage k chunk transposed: kt[d][s]
            for (int idx = tid; idx < 2048; idx += 256) {
                const int s = idx >> 4, dq = (idx & 15) << 2;
                const int g = ((s0 + s) * B_ + b) * NQKV_ + E_ + h * D_ + dq;
                const float4 kr = *reinterpret_cast<const float4*>(&qkvr[g]);
                const float4 ki = *reinterpret_cast<const float4*>(&qkvi[g]);
                bufA[(dq + 0) * 132 + s] = kr.x; bufA[(dq + 1) * 132 + s] = kr.y;
                bufA[(dq + 2) * 132 + s] = kr.z; bufA[(dq + 3) * 132 + s] = kr.w;
                bufB[(dq + 0) * 132 + s] = ki.x; bufB[(dq + 1) * 132 + s] = ki.y;
                bufB[(dq + 2) * 132 + s] = ki.z; bufB[(dq + 3) * 132 + s] = ki.w;
            }
            __syncthreads();

            float a1[2][4], a2[2][4];
#pragma unroll
            for (int i = 0; i < 2; i++)
#pragma unroll
                for (int j = 0; j < 4; j++) { a1[i][j] = 0.f; a2[i][j] = 0.f; }

#pragma unroll 4
            for (int d = 0; d < 64; d++) {
                const float qr0 = qtr[d * 16 + t0],     qi0 = qti[d * 16 + t0];
                const float qr1 = qtr[d * 16 + t0 + 1], qi1 = qti[d * 16 + t0 + 1];
                float kr[4], ki[4];
                *reinterpret_cast<float4*>(kr) = *reinterpret_cast<const float4*>(&bufA[d * 132 + sj]);
                *reinterpret_cast<float4*>(ki) = *reinterpret_cast<const float4*>(&bufB[d * 132 + sj]);
#pragma unroll
                for (int j = 0; j < 4; j++) {
                    a1[0][j] += qr0 * kr[j] + qi0 * ki[j];
                    a2[0][j] += qi0 * kr[j] - qr0 * ki[j];
                    a1[1][j] += qr1 * kr[j] + qi1 * ki[j];
                    a2[1][j] += qi1 * kr[j] - qr1 * ki[j];
                }
            }
#pragma unroll
            for (int i = 0; i < 2; i++) {
                float4 w1, w2;
                w1.x = a1[i][0] * SCALE_; w1.y = a1[i][1] * SCALE_;
                w1.z = a1[i][2] * SCALE_; w1.w = a1[i][3] * SCALE_;
                w2.x = a2[i][0] * SCALE_; w2.y = a2[i][1] * SCALE_;
                w2.z = a2[i][2] * SCALE_; w2.w = a2[i][3] * SCALE_;
                *reinterpret_cast<float4*>(&s1[(t0 + i) * 1024 + s0 + sj]) = w1;
                *reinterpret_cast<float4*>(&s2[(t0 + i) * 1024 + s0 + sj]) = w2;
            }
        }
    }
    __syncthreads();

    // ---- phase 2: softmax (32 rows: 16 of s1, 16 of s2) + aw average ----
    {
        const int warp = tid >> 5, lane = tid & 31;
        for (int r = warp; r < 32; r += 8) {
            float* row = (r < 16) ? &s1[r * 1024] : &s2[(r - 16) * 1024];
            float m = -INFINITY;
            for (int c = lane; c < 1024; c += 32) m = fmaxf(m, row[c]);
#pragma unroll
            for (int o = 16; o > 0; o >>= 1) m = fmaxf(m, __shfl_xor_sync(0xffffffffu, m, o));
            float sum = 0.f;
            for (int c = lane; c < 1024; c += 32) {
                const float e = __expf(row[c] - m);
                row[c] = e;
                sum += e;
            }
#pragma unroll
            for (int o = 16; o > 0; o >>= 1) sum += __shfl_xor_sync(0xffffffffu, sum, o);
            const float inv = 1.0f / sum;
            const int tg = tBlk + (r & 15);
            float* awbase = aw_out + ((r < 16) ? 0 : BTT_) + b * (T_ * T_) + tg * T_;
            for (int c = lane; c < 1024; c += 32) {
                const float p = row[c] * inv;
                row[c] = p;
                atomicAdd(&awbase[c], p * INV_H_);
            }
        }
    }
    __syncthreads();

    // ---- phase 3: attn = aw @ conj(v) ----
    {
        const int t3 = tid >> 4;            // 0..15
        const int dj = (tid & 15) << 2;     // 0..60
        float aR[4] = {0.f, 0.f, 0.f, 0.f};
        float aI[4] = {0.f, 0.f, 0.f, 0.f};
        for (int s0 = 0; s0 < 1024; s0 += 128) {
            __syncthreads();
            for (int idx = tid; idx < 2048; idx += 256) {
                const int s = idx >> 4, dq = (idx & 15) << 2;
                const int g = ((s0 + s) * B_ + b) * NQKV_ + 2 * E_ + h * D_ + dq;
                *reinterpret_cast<float4*>(&bufA[s * 68 + dq]) =
                    *reinterpret_cast<const float4*>(&qkvr[g]);
                *reinterpret_cast<float4*>(&bufB[s * 68 + dq]) =
                    *reinterpret_cast<const float4*>(&qkvi[g]);
            }
            __syncthreads();
#pragma unroll 4
            for (int s = 0; s < 128; s++) {
                const float awr = s1[t3 * 1024 + s0 + s];
                const float awi = s2[t3 * 1024 + s0 + s];
                float vr[4], vi[4];
                *reinterpret_cast<float4*>(vr) = *reinterpret_cast<const float4*>(&bufA[s * 68 + dj]);
                *reinterpret_cast<float4*>(vi) = *reinterpret_cast<const float4*>(&bufB[s * 68 + dj]);
#pragma unroll
                for (int j = 0; j < 4; j++) {
                    aR[j] += awr * vr[j] + awi * vi[j];
                    aI[j] += awi * vr[j] - awr * vi[j];
                }
            }
        }
        const int g = ((tBlk + t3) * B_ + b) * E_ + h * D_ + dj;
        float4 oR, oI;
        oR.x = aR[0]; oR.y = aR[1]; oR.z = aR[2]; oR.w = aR[3];
        oI.x = aI[0]; oI.y = aI[1]; oI.z = aI[2]; oI.w = aI[3];
        *reinterpret_cast<float4*>(&attnr[g]) = oR;
        *reinterpret_cast<float4*>(&attni[g]) = oI;
    }
}

// ---------------------------------------------------------------------------
// Launch
// ---------------------------------------------------------------------------
extern "C" void kernel_launch(void* const* d_in, const int* in_sizes, int n_in,
                              void* d_out, int out_size)
{
    const float* query_r = (const float*)d_in[0];
    const float* query_i = (const float*)d_in[1];
    const float* Wqkv_r  = (const float*)d_in[2];
    const float* Wqkv_i  = (const float*)d_in[3];
    const float* bqkv_r  = (const float*)d_in[4];
    const float* bqkv_i  = (const float*)d_in[5];
    const float* Wout_r  = (const float*)d_in[6];
    const float* Wout_i  = (const float*)d_in[7];
    const float* bout_r  = (const float*)d_in[8];
    const float* bout_i  = (const float*)d_in[9];
    float* out = (float*)d_out;

    float *qkvr, *qkvi, *atr, *ati;
    cudaGetSymbolAddress((void**)&qkvr, g_qkv_r);
    cudaGetSymbolAddress((void**)&qkvi, g_qkv_i);
    cudaGetSymbolAddress((void**)&atr,  g_attn_r);
    cudaGetSymbolAddress((void**)&ati,  g_attn_i);

    cudaFuncSetAttribute(attn_kernel,
                         cudaFuncAttributeMaxDynamicSharedMemorySize,
                         ATTN_SMEM_BYTES);

    // 1) zero the attention-weight-average output region (atomic accumulation)
    {
        const int n = 2 * BTT_;
        zero_kernel<<<(n + 255) / 256, 256>>>(out + OUT_AW_OFF_, n);
    }

    // 2) QKV complex linear: [8192,512] x [1536,512]^T
    cgemm64<<<dim3(NQKV_ / 64, TB_ / 64), 256>>>(
        query_r, query_i, Wqkv_r, Wqkv_i, bqkv_r, bqkv_i,
        qkvr, qkvi, TB_, NQKV_, E_);

    // 3) fused attention (scores + softmax + aw-average + PV)
    attn_kernel<<<dim3(T_ / 16, BH_), 256, ATTN_SMEM_BYTES>>>(
        qkvr, qkvi, atr, ati, out + OUT_AW_OFF_);

    // 4) output complex linear, writes out_r / out_i directly into d_out
    cgemm64<<<dim3(E_ / 64, TB_ / 64), 256>>>(
        atr, ati, Wout_r, Wout_i, bout_r, bout_i,
        out, out + TBE_, TB_, E_, E_);
}

// round 4
// speedup vs baseline: 1.0618x; 1.0618x over previous
#include <cuda_runtime.h>
#include <cuda_bf16.h>
#include <math.h>

// Problem constants
#define T_ 1024
#define B_ 8
#define E_ 512
#define H_ 8
#define D_ 64
#define BH_ 64          // B*H
#define TB_ 8192        // T*B
#define NQKV_ 1536      // 3*E
#define SCALE_ 0.125f   // D^-0.5
#define INV_H_ 0.125f

#define TBE_ (T_ * B_ * E_)          // 4,194,304
#define BTT_ (B_ * T_ * T_)          // 8,388,608
#define OUT_AW_OFF_ (2 * TBE_)       // start of aw stack in d_out
#define TT_ (T_ * T_)                // 1,048,576

// ---------------------------------------------------------------------------
// Scratch (device globals; no runtime allocation allowed).
// NOTE: total kept at ~134 MB — the 536 MB g_aw variant failed to even start
// the container twice; reverted to the atomic-accumulation aw path.
// ---------------------------------------------------------------------------
__device__ float g_qkv_r[TB_ * NQKV_];
__device__ float g_qkv_i[TB_ * NQKV_];
__device__ float g_attn_r[TB_ * E_];
__device__ float g_attn_i[TB_ * E_];

// ---------------------------------------------------------------------------
// Zero-fill kernel (aw-average region must start at 0 for atomic accumulation)
// ---------------------------------------------------------------------------
__global__ void zero_kernel(float* __restrict__ p, int n) {
    int i = blockIdx.x * blockDim.x + threadIdx.x;
    if (i < n) p[i] = 0.0f;
}

// ---------------------------------------------------------------------------
// Complex GEMM:  Y = X @ W^T + b   (complex), X:[M,K], W:[N,K], Y:[M,N]
// 64x64 tile, BK=16, 256 threads, 4x4 per thread. (71.5% fma in ncu — keep.)
// ---------------------------------------------------------------------------
__global__ __launch_bounds__(256) void cgemm64(
    const float* __restrict__ Xr, const float* __restrict__ Xi,
    const float* __restrict__ Wr, const float* __restrict__ Wi,
    const float* __restrict__ br, const float* __restrict__ bi,
    float* __restrict__ Yr, float* __restrict__ Yi,
    int M, int N, int K)
{
    __shared__ float sXr[16][68], sXi[16][68], sWr[16][68], sWi[16][68];

    const int tid  = threadIdx.x;
    const int row0 = blockIdx.y * 64;
    const int col0 = blockIdx.x * 64;
    const int lr = tid >> 2;
    const int lk = (tid & 3) << 2;
    const int ty = tid >> 4;
    const int tx = tid & 15;

    float accr[4][4], acci[4][4];
#pragma unroll
    for (int i = 0; i < 4; i++)
#pragma unroll
        for (int j = 0; j < 4; j++) { accr[i][j] = 0.f; acci[i][j] = 0.f; }

    for (int k0 = 0; k0 < K; k0 += 16) {
        float4 v;
        v = *reinterpret_cast<const float4*>(&Xr[(row0 + lr) * K + k0 + lk]);
        sXr[lk + 0][lr] = v.x; sXr[lk + 1][lr] = v.y; sXr[lk + 2][lr] = v.z; sXr[lk + 3][lr] = v.w;
        v = *reinterpret_cast<const float4*>(&Xi[(row0 + lr) * K + k0 + lk]);
        sXi[lk + 0][lr] = v.x; sXi[lk + 1][lr] = v.y; sXi[lk + 2][lr] = v.z; sXi[lk + 3][lr] = v.w;
        v = *reinterpret_cast<const float4*>(&Wr[(col0 + lr) * K + k0 + lk]);
        sWr[lk + 0][lr] = v.x; sWr[lk + 1][lr] = v.y; sWr[lk + 2][lr] = v.z; sWr[lk + 3][lr] = v.w;
        v = *reinterpret_cast<const float4*>(&Wi[(col0 + lr) * K + k0 + lk]);
        sWi[lk + 0][lr] = v.x; sWi[lk + 1][lr] = v.y; sWi[lk + 2][lr] = v.z; sWi[lk + 3][lr] = v.w;
        __syncthreads();

#pragma unroll
        for (int k = 0; k < 16; k++) {
            float ar[4], ai[4], wr[4], wi[4];
            *reinterpret_cast<float4*>(ar) = *reinterpret_cast<const float4*>(&sXr[k][ty << 2]);
            *reinterpret_cast<float4*>(ai) = *reinterpret_cast<const float4*>(&sXi[k][ty << 2]);
            *reinterpret_cast<float4*>(wr) = *reinterpret_cast<const float4*>(&sWr[k][tx << 2]);
            *reinterpret_cast<float4*>(wi) = *reinterpret_cast<const float4*>(&sWi[k][tx << 2]);
#pragma unroll
            for (int i = 0; i < 4; i++)
#pragma unroll
                for (int j = 0; j < 4; j++) {
                    accr[i][j] += ar[i] * wr[j] - ai[i] * wi[j];
                    acci[i][j] += ai[i] * wr[j] + ar[i] * wi[j];
                }
        }
        __syncthreads();
    }

    const float4 b4r = *reinterpret_cast<const float4*>(&br[col0 + (tx << 2)]);
    const float4 b4i = *reinterpret_cast<const float4*>(&bi[col0 + (tx << 2)]);
#pragma unroll
    for (int i = 0; i < 4; i++) {
        const int row = row0 + (ty << 2) + i;
        float4 orr, oii;
        orr.x = accr[i][0] + b4r.x; orr.y = accr[i][1] + b4r.y;
        orr.z = accr[i][2] + b4r.z; orr.w = accr[i][3] + b4r.w;
        oii.x = acci[i][0] + b4i.x; oii.y = acci[i][1] + b4i.y;
        oii.z = acci[i][2] + b4i.z; oii.w = acci[i][3] + b4i.w;
        *reinterpret_cast<float4*>(&Yr[row * N + col0 + (tx << 2)]) = orr;
        *reinterpret_cast<float4*>(&Yi[row * N + col0 + (tx << 2)]) = oii;
    }
}

// ---------------------------------------------------------------------------
// Fused attention, v2. CTA = (16 q-rows, one (b,h)).
//   phase 1: scores via 4q x 4s per thread, d-split across 2 thread groups
//   phase 2: softmax; atomic-accumulates head-average into d_out aw region
//   phase 3: PV via 4q x 4d per thread, 4-way s-split + smem reduce
// ---------------------------------------------------------------------------
#define TQ_ 16
#define ATTN_SMEM_FLOATS (2*TQ_*1024 + 2*1024 + 2*8704)
#define ATTN_SMEM_BYTES  (ATTN_SMEM_FLOATS * 4)   // 208,896 B

__global__ __launch_bounds__(256) void attn_kernel(
    const float* __restrict__ qkvr, const float* __restrict__ qkvi,
    float* __restrict__ attnr, float* __restrict__ attni,
    float* __restrict__ aw_out)
{
    extern __shared__ float sh[];
    float* s1   = sh;                       // [16][1024]
    float* s2   = s1 + TQ_ * 1024;          // [16][1024]
    float* qtr  = s2 + TQ_ * 1024;          // [64][16]
    float* qti  = qtr + 1024;               // [64][16]
    float* bufA = qti + 1024;               // 8704 floats (k_r^T / v_r / staging)
    float* bufB = bufA + 8704;              // 8704 floats (k_i^T / v_i / staging)

    const int tid  = threadIdx.x;
    const int tBlk = blockIdx.x * TQ_;
    const int bh   = blockIdx.y;
    const int b    = bh >> 3;
    const int h    = bh & 7;

    // ---- load q tile (transposed: qtr[d*16 + t]) ----
    for (int idx = tid; idx < 1024; idx += 256) {
        const int t = idx >> 6, d = idx & 63;
        const int g = ((tBlk + t) * B_ + b) * NQKV_ + h * D_ + d;
        qtr[d * 16 + t] = qkvr[g];
        qti[d * 16 + t] = qkvi[g];
    }

    // ---- phase 1: scores ----
    {
        const int dgrp = tid >> 7;           // 0/1 : d-halves
        const int t7   = tid & 127;
        const int qg   = t7 >> 5;            // 0..3 -> q rows qg*4..+3
        const int sl   = t7 & 31;            // s cols sl*4..+3 within chunk
        const int d0   = dgrp * 32;

        for (int s0 = 0; s0 < 1024; s0 += 128) {
            __syncthreads();   // protects bufA/bufB reuse from prev iteration
            // stage k chunk transposed: kT[d][s], stride 132
            for (int idx = tid; idx < 2048; idx += 256) {
                const int s = idx >> 4, dq = (idx & 15) << 2;
                const int g = ((s0 + s) * B_ + b) * NQKV_ + E_ + h * D_ + dq;
                const float4 kr = *reinterpret_cast<const float4*>(&qkvr[g]);
                const float4 ki = *reinterpret_cast<const float4*>(&qkvi[g]);
                bufA[(dq + 0) * 132 + s] = kr.x; bufA[(dq + 1) * 132 + s] = kr.y;
                bufA[(dq + 2) * 132 + s] = kr.z; bufA[(dq + 3) * 132 + s] = kr.w;
                bufB[(dq + 0) * 132 + s] = ki.x; bufB[(dq + 1) * 132 + s] = ki.y;
                bufB[(dq + 2) * 132 + s] = ki.z; bufB[(dq + 3) * 132 + s] = ki.w;
            }
            __syncthreads();

            float a1[4][4], a2[4][4];
#pragma unroll
            for (int i = 0; i < 4; i++)
#pragma unroll
                for (int j = 0; j < 4; j++) { a1[i][j] = 0.f; a2[i][j] = 0.f; }

#pragma unroll 4
            for (int dd = 0; dd < 32; dd++) {
                const int d = d0 + dd;
                float qr[4], qi4[4], kr[4], ki[4];
                *reinterpret_cast<float4*>(qr)  = *reinterpret_cast<const float4*>(&qtr[d * 16 + (qg << 2)]);
                *reinterpret_cast<float4*>(qi4) = *reinterpret_cast<const float4*>(&qti[d * 16 + (qg << 2)]);
                *reinterpret_cast<float4*>(kr)  = *reinterpret_cast<const float4*>(&bufA[d * 132 + (sl << 2)]);
                *reinterpret_cast<float4*>(ki)  = *reinterpret_cast<const float4*>(&bufB[d * 132 + (sl << 2)]);
#pragma unroll
                for (int i = 0; i < 4; i++)
#pragma unroll
                    for (int j = 0; j < 4; j++) {
                        a1[i][j] += qr[i]  * kr[j] + qi4[i] * ki[j];
                        a2[i][j] += qi4[i] * kr[j] - qr[i]  * ki[j];
                    }
            }

            __syncthreads();   // k reads done; bufA/bufB free for staging
            if (dgrp == 1) {
#pragma unroll
                for (int i = 0; i < 4; i++) {
                    const int row = (qg << 2) + i;
                    *reinterpret_cast<float4*>(&bufA[row * 128 + (sl << 2)]) =
                        *reinterpret_cast<float4*>(a1[i]);
                    *reinterpret_cast<float4*>(&bufB[row * 128 + (sl << 2)]) =
                        *reinterpret_cast<float4*>(a2[i]);
                }
            }
            __syncthreads();
            if (dgrp == 0) {
#pragma unroll
                for (int i = 0; i < 4; i++) {
                    const int row = (qg << 2) + i;
                    float4 p1 = *reinterpret_cast<const float4*>(&bufA[row * 128 + (sl << 2)]);
                    float4 p2 = *reinterpret_cast<const float4*>(&bufB[row * 128 + (sl << 2)]);
                    float4 w1, w2;
                    w1.x = (a1[i][0] + p1.x) * SCALE_; w1.y = (a1[i][1] + p1.y) * SCALE_;
                    w1.z = (a1[i][2] + p1.z) * SCALE_; w1.w = (a1[i][3] + p1.w) * SCALE_;
                    w2.x = (a2[i][0] + p2.x) * SCALE_; w2.y = (a2[i][1] + p2.y) * SCALE_;
                    w2.z = (a2[i][2] + p2.z) * SCALE_; w2.w = (a2[i][3] + p2.w) * SCALE_;
                    *reinterpret_cast<float4*>(&s1[row * 1024 + s0 + (sl << 2)]) = w1;
                    *reinterpret_cast<float4*>(&s2[row * 1024 + s0 + (sl << 2)]) = w2;
                }
            }
        }
    }
    __syncthreads();

    // ---- phase 2: softmax (32 rows) + atomic head-average accumulation ----
    {
        const int warp = tid >> 5, lane = tid & 31;
        for (int r = warp; r < 32; r += 8) {
            float* row = (r < 16) ? &s1[r * 1024] : &s2[(r - 16) * 1024];
            float m = -INFINITY;
            for (int c = lane; c < 1024; c += 32) m = fmaxf(m, row[c]);
#pragma unroll
            for (int o = 16; o > 0; o >>= 1) m = fmaxf(m, __shfl_xor_sync(0xffffffffu, m, o));
            float sum = 0.f;
            for (int c = lane; c < 1024; c += 32) {
                const float e = __expf(row[c] - m);
                row[c] = e;
                sum += e;
            }
#pragma unroll
            for (int o = 16; o > 0; o >>= 1) sum += __shfl_xor_sync(0xffffffffu, sum, o);
            const float inv = 1.0f / sum;
            const int tg = tBlk + (r & 15);
            float* awbase = aw_out + ((r < 16) ? 0 : BTT_) + b * TT_ + tg * T_;
            for (int c = lane; c < 1024; c += 32) {
                const float p = row[c] * inv;
                row[c] = p;
                atomicAdd(&awbase[c], p * INV_H_);
            }
        }
    }

    // ---- phase 3: attn = aw @ conj(v), 4-way s-split ----
    {
        const int g3 = tid >> 6;            // 0..3 : s-quarter of each chunk
        const int t6 = tid & 63;
        const int qg = t6 >> 4;             // 0..3 -> q rows qg*4..+3
        const int dg = t6 & 15;             // d cols dg*4..+3

        float cr[4][4], ci[4][4];
#pragma unroll
        for (int i = 0; i < 4; i++)
#pragma unroll
            for (int j = 0; j < 4; j++) { cr[i][j] = 0.f; ci[i][j] = 0.f; }

        for (int s0 = 0; s0 < 1024; s0 += 128) {
            __syncthreads();   // also orders softmax writes before first read
            for (int idx = tid; idx < 2048; idx += 256) {
                const int s = idx >> 4, dq = (idx & 15) << 2;
                const int g = ((s0 + s) * B_ + b) * NQKV_ + 2 * E_ + h * D_ + dq;
                *reinterpret_cast<float4*>(&bufA[s * 68 + dq]) =
                    *reinterpret_cast<const float4*>(&qkvr[g]);
                *reinterpret_cast<float4*>(&bufB[s * 68 + dq]) =
                    *reinterpret_cast<const float4*>(&qkvi[g]);
            }
            __syncthreads();

#pragma unroll 4
            for (int ss = 0; ss < 32; ss++) {
                const int s = (g3 << 5) + ss;          // within chunk
                float vr[4], vi[4];
                *reinterpret_cast<float4*>(vr) = *reinterpret_cast<const float4*>(&bufA[s * 68 + (dg << 2)]);
                *reinterpret_cast<float4*>(vi) = *reinterpret_cast<const float4*>(&bufB[s * 68 + (dg << 2)]);
#pragma unroll
                for (int i = 0; i < 4; i++) {
                    const float awr = s1[((qg << 2) + i) * 1024 + s0 + s];
                    const float awi = s2[((qg << 2) + i) * 1024 + s0 + s];
#pragma unroll
                    for (int j = 0; j < 4; j++) {
                        cr[i][j] += awr * vr[j] + awi * vi[j];
                        ci[i][j] += awi * vr[j] - awr * vi[j];
                    }
                }
            }
        }

        // reduce 4 s-partials via smem staging (bufA: cr, bufB: ci)
        __syncthreads();
        if (g3 > 0) {
#pragma unroll
            for (int i = 0; i < 4; i++) {
                const int off = (g3 - 1) * 2048 + ((qg << 2) + i) * 64 + (dg << 2);
                *reinterpret_cast<float4*>(&bufA[off]) = *reinterpret_cast<float4*>(cr[i]);
                *reinterpret_cast<float4*>(&bufB[off]) = *reinterpret_cast<float4*>(ci[i]);
            }
        }
        __syncthreads();
        if (g3 == 0) {
#pragma unroll
            for (int i = 0; i < 4; i++) {
                const int row = (qg << 2) + i;
                float4 aR = *reinterpret_cast<float4*>(cr[i]);
                float4 aI = *reinterpret_cast<float4*>(ci[i]);
#pragma unroll
                for (int p = 0; p < 3; p++) {
                    const int off = p * 2048 + row * 64 + (dg << 2);
                    float4 pr = *reinterpret_cast<const float4*>(&bufA[off]);
                    float4 pi = *reinterpret_cast<const float4*>(&bufB[off]);
                    aR.x += pr.x; aR.y += pr.y; aR.z += pr.z; aR.w += pr.w;
                    aI.x += pi.x; aI.y += pi.y; aI.z += pi.z; aI.w += pi.w;
                }
                const int g = ((tBlk + row) * B_ + b) * E_ + h * D_ + (dg << 2);
                *reinterpret_cast<float4*>(&attnr[g]) = aR;
                *reinterpret_cast<float4*>(&attni[g]) = aI;
            }
        }
    }
}

// ---------------------------------------------------------------------------
// Launch
// ---------------------------------------------------------------------------
extern "C" void kernel_launch(void* const* d_in, const int* in_sizes, int n_in,
                              void* d_out, int out_size)
{
    const float* query_r = (const float*)d_in[0];
    const float* query_i = (const float*)d_in[1];
    const float* Wqkv_r  = (const float*)d_in[2];
    const float* Wqkv_i  = (const float*)d_in[3];
    const float* bqkv_r  = (const float*)d_in[4];
    const float* bqkv_i  = (const float*)d_in[5];
    const float* Wout_r  = (const float*)d_in[6];
    const float* Wout_i  = (const float*)d_in[7];
    const float* bout_r  = (const float*)d_in[8];
    const float* bout_i  = (const float*)d_in[9];
    float* out = (float*)d_out;

    float *qkvr, *qkvi, *atr, *ati;
    cudaGetSymbolAddress((void**)&qkvr, g_qkv_r);
    cudaGetSymbolAddress((void**)&qkvi, g_qkv_i);
    cudaGetSymbolAddress((void**)&atr,  g_attn_r);
    cudaGetSymbolAddress((void**)&ati,  g_attn_i);

    cudaFuncSetAttribute(attn_kernel,
                         cudaFuncAttributeMaxDynamicSharedMemorySize,
                         ATTN_SMEM_BYTES);

    // 1) zero the attention-weight-average output region (atomic accumulation)
    {
        const int n = 2 * BTT_;
        zero_kernel<<<(n + 255) / 256, 256>>>(out + OUT_AW_OFF_, n);
    }

    // 2) QKV complex linear: [8192,512] x [1536,512]^T
    cgemm64<<<dim3(NQKV_ / 64, TB_ / 64), 256>>>(
        query_r, query_i, Wqkv_r, Wqkv_i, bqkv_r, bqkv_i,
        qkvr, qkvi, TB_, NQKV_, E_);

    // 3) fused attention (scores + softmax + aw atomic average + PV)
    attn_kernel<<<dim3(T_ / TQ_, BH_), 256, ATTN_SMEM_BYTES>>>(
        qkvr, qkvi, atr, ati, out + OUT_AW_OFF_);

    // 4) output complex linear, writes out_r / out_i directly into d_out
    cgemm64<<<dim3(E_ / 64, TB_ / 64), 256>>>(
        atr, ati, Wout_r, Wout_i, bout_r, bout_i,
        out, out + TBE_, TB_, E_, E_);
}